// round 15
// baseline (speedup 1.0000x reference)
#include <cuda_runtime.h>
#include <math.h>

// ---------------------------------------------------------------------------
// Problem: BiGRU encoder. B=32, T=1024, N=512.
// Phase 1: gi[dir][t][b][3N] = x_slice @ Wih^T + bih   (big parallel GEMM)
// Phase 2: persistent kernel, 64 CTAs per direction, grid barrier per step.
// ---------------------------------------------------------------------------

__device__ float g_gi[2ull * 32768ull * 1536ull];   // [dir][t*32+b][3N]
__device__ float g_h[2 * 2 * 512 * 32];             // [dir][parity][k][b]
__device__ unsigned g_count[2];
__device__ unsigned g_release[2];

union F2 { float2 f; unsigned long long u; };

__device__ __forceinline__ void fma2(F2& d, F2 a, F2 b) {
    asm("fma.rn.f32x2 %0, %1, %2, %0;" : "+l"(d.u) : "l"(a.u), "l"(b.u));
}
__device__ __forceinline__ F2 splat2(float v) { F2 r; r.f = make_float2(v, v); return r; }

__device__ __forceinline__ float fsig(float v) { return 1.0f / (1.0f + __expf(-v)); }
__device__ __forceinline__ float ftanh(float v) {
    float a = fabsf(v);
    float e = __expf(-2.0f * a);
    float t = (1.0f - e) / (1.0f + e);
    return copysignf(t, v);
}

// ---------------------------------------------------------------------------
__global__ void init_state() {
    int i = blockIdx.x * blockDim.x + threadIdx.x;
    if (i < 2 * 2 * 512 * 32) g_h[i] = 0.0f;
    if (i < 2) { g_count[i] = 0u; g_release[i] = 0u; }
}

// ---------------------------------------------------------------------------
// Phase 1 GEMM: C[m][j] = sum_k A[m][k] * W[j][k] + bih[j]
//   m = t*32 + b, A[m][k] = x[b][tt][k], tt = dir ? 1023-t : t
// BM=BN=128, BK=16, 256 threads, 8x8 thread tile via f32x2.
// ---------------------------------------------------------------------------
__global__ void __launch_bounds__(256) gi_gemm(
    const float* __restrict__ x,
    const float* __restrict__ WihF, const float* __restrict__ WihB,
    const float* __restrict__ bihF, const float* __restrict__ bihB)
{
    __shared__ float As[16][128];
    __shared__ float Bs[16][128];

    const int d   = blockIdx.z;
    const float* __restrict__ W   = d ? WihB : WihF;
    const float* __restrict__ bih = d ? bihB : bihF;
    const int j0  = blockIdx.x * 128;
    const int m0  = blockIdx.y * 128;
    const int tid = threadIdx.x;

    int rowA[2], kqA[2];
    const float* aptr[2];
    const float* bptr[2];
    #pragma unroll
    for (int h = 0; h < 2; ++h) {
        int idx = tid + 256 * h;
        int row = idx >> 2, kq = idx & 3;
        rowA[h] = row; kqA[h] = kq;
        int m = m0 + row;
        int b = m & 31, t = m >> 5;
        int tt = d ? (1023 - t) : t;
        aptr[h] = x + ((size_t)b * 1024 + tt) * 512 + kq * 4;
        bptr[h] = W + (size_t)(j0 + row) * 512 + kq * 4;
    }
    const int ty = tid >> 4, tx = tid & 15;

    F2 c[8][4];
    #pragma unroll
    for (int r = 0; r < 8; ++r)
        #pragma unroll
        for (int q = 0; q < 4; ++q) c[r][q].f = make_float2(0.f, 0.f);

    float4 pa[2], pb[2];
    #pragma unroll
    for (int h = 0; h < 2; ++h) {
        pa[h] = *(const float4*)(aptr[h]);
        pb[h] = *(const float4*)(bptr[h]);
    }

    for (int kt = 0; kt < 32; ++kt) {
        __syncthreads();
        #pragma unroll
        for (int h = 0; h < 2; ++h) {
            int kk = kqA[h] * 4, rw = rowA[h];
            As[kk + 0][rw] = pa[h].x; As[kk + 1][rw] = pa[h].y;
            As[kk + 2][rw] = pa[h].z; As[kk + 3][rw] = pa[h].w;
            Bs[kk + 0][rw] = pb[h].x; Bs[kk + 1][rw] = pb[h].y;
            Bs[kk + 2][rw] = pb[h].z; Bs[kk + 3][rw] = pb[h].w;
        }
        __syncthreads();
        if (kt < 31) {
            #pragma unroll
            for (int h = 0; h < 2; ++h) {
                pa[h] = *(const float4*)(aptr[h] + (kt + 1) * 16);
                pb[h] = *(const float4*)(bptr[h] + (kt + 1) * 16);
            }
        }
        #pragma unroll
        for (int kk = 0; kk < 16; ++kk) {
            float4 alo = *(const float4*)&As[kk][ty * 4];
            float4 ahi = *(const float4*)&As[kk][64 + ty * 4];
            float4 blo = *(const float4*)&Bs[kk][tx * 4];
            float4 bhi = *(const float4*)&Bs[kk][64 + tx * 4];
            float av[8] = {alo.x, alo.y, alo.z, alo.w, ahi.x, ahi.y, ahi.z, ahi.w};
            F2 bv[4];
            bv[0].f = make_float2(blo.x, blo.y); bv[1].f = make_float2(blo.z, blo.w);
            bv[2].f = make_float2(bhi.x, bhi.y); bv[3].f = make_float2(bhi.z, bhi.w);
            #pragma unroll
            for (int r = 0; r < 8; ++r) {
                F2 a2 = splat2(av[r]);
                #pragma unroll
                for (int q = 0; q < 4; ++q) fma2(c[r][q], a2, bv[q]);
            }
        }
    }

    int cols[4] = { j0 + tx * 4, j0 + tx * 4 + 2, j0 + 64 + tx * 4, j0 + 64 + tx * 4 + 2 };
    float2 bias[4];
    #pragma unroll
    for (int q = 0; q < 4; ++q) bias[q] = *(const float2*)(bih + cols[q]);

    #pragma unroll
    for (int r = 0; r < 8; ++r) {
        int m = m0 + ((r < 4) ? (ty * 4 + r) : (64 + ty * 4 + (r - 4)));
        float* orow = g_gi + ((size_t)(d * 32768 + m)) * 1536;
        #pragma unroll
        for (int q = 0; q < 4; ++q) {
            float2 v = c[r][q].f;
            v.x += bias[q].x; v.y += bias[q].y;
            *(float2*)(orow + cols[q]) = v;
        }
    }
}

// ---------------------------------------------------------------------------
// Transpose-reduce: each lane holds partials a[0..31] (index = batch).
// After 5 compacting stages, lane l holds the full sum for batch l in a[0].
// 31 shfl + 31 add per 32-wide reduce. All indices static.
// ---------------------------------------------------------------------------
template<int M>
__device__ __forceinline__ void red_stage(float* a, int lane) {
    #pragma unroll
    for (int i = 0; i < M; ++i) {
        float mine  = (lane & M) ? a[i + M] : a[i];
        float other = (lane & M) ? a[i]     : a[i + M];
        float recv  = __shfl_xor_sync(0xffffffffu, other, M);
        a[i] = mine + recv;
    }
}
__device__ __forceinline__ float reduce32(float* a, int lane) {
    red_stage<16>(a, lane); red_stage<8>(a, lane); red_stage<4>(a, lane);
    red_stage<2>(a, lane);  red_stage<1>(a, lane);
    return a[0];
}

// ---------------------------------------------------------------------------
// Phase 2: persistent recurrent kernel. 128 CTAs (dir = blockIdx.x>>6).
// Warp w of CTA c owns hidden column i = c*8+w; Whh rows in registers.
// h_s layout: [k][b] with row stride 34 floats (conflict-free LDS.64 pairs).
// ---------------------------------------------------------------------------
__global__ void __launch_bounds__(256, 1) recurrent(
    const float* __restrict__ x,
    const float* __restrict__ WhhF, const float* __restrict__ WhhB,
    const float* __restrict__ bhhF, const float* __restrict__ bhhB,
    float* __restrict__ out)
{
    extern __shared__ float h_s[];   // 512 * 34 floats

    const int d    = blockIdx.x >> 6;
    const int c    = blockIdx.x & 63;
    const int tid  = threadIdx.x;
    const int w    = tid >> 5, lane = tid & 31;
    const int i_col = c * 8 + w;

    const float* __restrict__ Whh = d ? WhhB : WhhF;
    const float* __restrict__ bhh = d ? bhhB : bhhF;

    float Wr[16], Wz[16], Wn[16];
    #pragma unroll
    for (int j = 0; j < 16; ++j) {
        int k = lane + 32 * j;
        Wr[j] = Whh[(size_t)(0 * 512 + i_col) * 512 + k];
        Wz[j] = Whh[(size_t)(1 * 512 + i_col) * 512 + k];
        Wn[j] = Whh[(size_t)(2 * 512 + i_col) * 512 + k];
    }
    const float bhr = bhh[i_col], bhz = bhh[512 + i_col], bhn = bhh[1024 + i_col];

    const float* __restrict__ gi_base = g_gi + (size_t)d * 32768 * 1536;

    for (int t = 0; t < 1024; ++t) {
        // --- load full h (64KB) from global (k-major) into smem [k][b], stride 34
        const float4* __restrict__ hg = (const float4*)(g_h + ((d * 2 + (t & 1)) << 14));
        #pragma unroll
        for (int u = 0; u < 16; ++u) {
            int v = tid + 256 * u;
            float4 hv = __ldcg(hg + v);
            int k = v >> 3, b0 = (v & 7) * 4;
            float2* dst = (float2*)(h_s + k * 34 + b0);
            dst[0] = make_float2(hv.x, hv.y);
            dst[1] = make_float2(hv.z, hv.w);
        }
        // --- prefetch epilogue operands (b = lane, i = i_col); latency hidden by MAC
        const float* gp = gi_base + ((size_t)(t * 32 + lane)) * 1536 + i_col;
        float gir = __ldg(gp), giz = __ldg(gp + 512), gin = __ldg(gp + 1024);
        int tt = d ? (1023 - t) : t;
        float xv = __ldg(x + ((size_t)lane * 1024 + tt) * 512 + i_col);
        __syncthreads();

        // --- MAC: gh[g][b] = sum_k Whh[g][i_col][k] * h[b][k], b in float2 pairs
        F2 ar[16], az[16], an[16];
        #pragma unroll
        for (int bp = 0; bp < 16; ++bp) {
            ar[bp].f = make_float2(0.f, 0.f);
            az[bp].f = make_float2(0.f, 0.f);
            an[bp].f = make_float2(0.f, 0.f);
        }
        #pragma unroll
        for (int j = 0; j < 16; ++j) {
            const float2* hp = (const float2*)(h_s + (lane + 32 * j) * 34);
            F2 wr2 = splat2(Wr[j]), wz2 = splat2(Wz[j]), wn2 = splat2(Wn[j]);
            #pragma unroll
            for (int bp = 0; bp < 16; ++bp) {
                F2 hv; hv.f = hp[bp];
                fma2(ar[bp], wr2, hv);
                fma2(az[bp], wz2, hv);
                fma2(an[bp], wn2, hv);
            }
        }

        // --- cross-lane reduce; lane l ends with totals for batch l
        float vr[32], vz[32], vn[32];
        #pragma unroll
        for (int bp = 0; bp < 16; ++bp) {
            vr[2 * bp] = ar[bp].f.x; vr[2 * bp + 1] = ar[bp].f.y;
            vz[2 * bp] = az[bp].f.x; vz[2 * bp + 1] = az[bp].f.y;
            vn[2 * bp] = an[bp].f.x; vn[2 * bp + 1] = an[bp].f.y;
        }
        float ghr = reduce32(vr, lane);
        float ghz = reduce32(vz, lane);
        float ghn = reduce32(vn, lane);

        // --- gates for (b = lane, i = i_col)
        float r  = fsig(gir + ghr + bhr);
        float z  = fsig(giz + ghz + bhz);
        float nn = ftanh(gin + r * (ghn + bhn));
        float hold = h_s[i_col * 34 + lane];
        float hnew = (1.0f - z) * nn + z * hold;

        float* hw = g_h + ((d * 2 + ((t & 1) ^ 1)) << 14);
        __stcg(hw + i_col * 32 + lane, hnew);
        out[((size_t)lane * 1024 + t) * 1024 + d * 512 + i_col] = hnew + xv;

        // --- grid barrier across this direction's 64 CTAs (sense via monotone release)
        __syncthreads();
        if (tid == 0) {
            __threadfence();
            unsigned arr = atomicAdd(&g_count[d], 1u);
            if (arr == 63u) {
                atomicExch(&g_count[d], 0u);
                __threadfence();
                atomicAdd(&g_release[d], 1u);
            } else {
                volatile unsigned* rel = &g_release[d];
                unsigned tgt = (unsigned)(t + 1);
                while (*rel < tgt) { }
                __threadfence();
            }
        }
        __syncthreads();
    }
}

// ---------------------------------------------------------------------------
extern "C" void kernel_launch(void* const* d_in, const int* in_sizes, int n_in,
                              void* d_out, int out_size) {
    const float* x    = (const float*)d_in[0];
    const float* WihF = (const float*)d_in[1];
    const float* WhhF = (const float*)d_in[2];
    const float* bihF = (const float*)d_in[3];
    const float* bhhF = (const float*)d_in[4];
    const float* WihB = (const float*)d_in[5];
    const float* WhhB = (const float*)d_in[6];
    const float* bihB = (const float*)d_in[7];
    const float* bhhB = (const float*)d_in[8];
    float* out = (float*)d_out;

    cudaFuncSetAttribute(recurrent, cudaFuncAttributeMaxDynamicSharedMemorySize, 512 * 34 * 4);

    init_state<<<256, 256>>>();
    gi_gemm<<<dim3(12, 256, 2), 256>>>(x, WihF, WihB, bihF, bihB);
    recurrent<<<128, 256, 512 * 34 * 4>>>(x, WhhF, WhhB, bhhF, bhhB, out);
}